// round 16
// baseline (speedup 1.0000x reference)
#include <cuda_runtime.h>
#include <cuda_bf16.h>
#include <cstddef>
#include <cstdint>

// ---------------------------------------------------------------------------
// SpatialGCN: 2-layer GCN, N=100000, E=800000, 128 -> 256 -> 128.
//   layer1: relu( agg(x) @ W1 + b1 )   [aggregate BEFORE GEMM, 128-dim]
//   layer2: agg( h @ W2 ) + b2         [aggregate AFTER GEMM, 128-dim]
// FUSED GEMM: one persistent kernel does GEMM1 -> (bias,relu,split) into
// SMEM -> GEMM2. mma.sync m16n8k16 bf16 hi/lo split, fp32 acc.
// Aggregation: CSR gather, TWO warps per node (64 dims / warp, float2 lanes)
// to double independent load chains.
// ---------------------------------------------------------------------------

#define N_NODES 100000
#define N_EDGES 800000
#define IN_DIM 128
#define HID_DIM 256
#define OUT_DIM 128
#define MTILES ((N_NODES + 127) / 128)     // 782
#define GRID_P 148

typedef __nv_bfloat16 bf16;

#define EDGE_BLOCKS ((N_EDGES + 255) / 256)
#define PREP_ELEMS (IN_DIM * HID_DIM + HID_DIM * OUT_DIM)
#define PREP_BLOCKS ((PREP_ELEMS + 255) / 256)

// -------------------- device scratch (static, no allocs) -------------------
__device__ float g_deg[N_NODES];           // zero at entry; re-zeroed at end
__device__ int   g_cnt[N_NODES];
__device__ float g_dis[N_NODES];
__device__ int   g_off[N_NODES + 1];
__device__ int   g_cur[N_NODES];
__device__ int   g_csr_src[N_EDGES];
__device__ float g_csr_nrm[N_EDGES];

__device__ bf16  g_a1h[(size_t)N_NODES * IN_DIM];
__device__ bf16  g_a1l[(size_t)N_NODES * IN_DIM];
__device__ float g_h2[(size_t)N_NODES * OUT_DIM];

__device__ bf16  g_w1th[HID_DIM * IN_DIM];
__device__ bf16  g_w1tl[HID_DIM * IN_DIM];
__device__ bf16  g_w2th[OUT_DIM * HID_DIM];
__device__ bf16  g_w2tl[OUT_DIM * HID_DIM];

// ------------------------------ PTX helpers --------------------------------

__device__ __forceinline__ uint32_t smem_u32(const void* p)
{
    uint32_t a;
    asm("{ .reg .u64 t; cvta.to.shared.u64 t, %1; cvt.u32.u64 %0, t; }"
        : "=r"(a) : "l"(p));
    return a;
}

__device__ __forceinline__ void cp_async16(uint32_t saddr, const void* gptr)
{
    asm volatile("cp.async.cg.shared.global [%0], [%1], 16;"
                 :: "r"(saddr), "l"(__cvta_generic_to_global(gptr)));
}
__device__ __forceinline__ void cp_commit()
{
    asm volatile("cp.async.commit_group;");
}
__device__ __forceinline__ void cp_wait0()
{
    asm volatile("cp.async.wait_group 0;");
}

__device__ __forceinline__ void ldmx4(uint32_t& r0, uint32_t& r1,
                                      uint32_t& r2, uint32_t& r3, uint32_t a)
{
    asm volatile("ldmatrix.sync.aligned.m8n8.x4.shared.b16 {%0,%1,%2,%3}, [%4];"
                 : "=r"(r0), "=r"(r1), "=r"(r2), "=r"(r3) : "r"(a));
}

__device__ __forceinline__ void mma_bf16(float* d, const uint32_t* a,
                                         uint32_t b0, uint32_t b1)
{
    asm volatile(
        "mma.sync.aligned.m16n8k16.row.col.f32.bf16.bf16.f32 "
        "{%0,%1,%2,%3}, {%4,%5,%6,%7}, {%8,%9}, {%0,%1,%2,%3};"
        : "+f"(d[0]), "+f"(d[1]), "+f"(d[2]), "+f"(d[3])
        : "r"(a[0]), "r"(a[1]), "r"(a[2]), "r"(a[3]), "r"(b0), "r"(b1));
}

__device__ __forceinline__ unsigned short bf_bits(bf16 h)
{
    return *(unsigned short*)&h;
}

// --------------------- per-block edge-dtype detection ----------------------

__device__ __forceinline__ int detect_is64_block(const void* ei)
{
    __shared__ int s_is64;
    int t = threadIdx.x;
    int ok = 1;
    if (t < 16) {
        const long long* p = (const long long*)ei;
        long long a = p[t];
        long long b = p[N_EDGES + t];
        if (a < 0 || a >= N_NODES || b < 0 || b >= N_NODES) ok = 0;
    }
    unsigned bad = __ballot_sync(0xffffffffu, ok == 0);
    if (t == 0) s_is64 = (bad == 0u);
    __syncthreads();
    return s_is64;
}

__device__ __forceinline__ int edge_row(const void* ei, int e, int is64)
{
    if (is64) return (int)((const long long*)ei)[e];
    return ((const int*)ei)[e];
}
__device__ __forceinline__ int edge_col(const void* ei, int e, int is64)
{
    if (is64) return (int)((const long long*)ei)[N_EDGES + e];
    return ((const int*)ei)[N_EDGES + e];
}

// ---------------- launch 1: deg/cnt accumulation + weight prep -------------

__global__ void k_deg_prep(const void* __restrict__ ei,
                           const float* __restrict__ w,
                           const float* __restrict__ W1,
                           const float* __restrict__ W2)
{
    if (blockIdx.x < EDGE_BLOCKS) {
        int is64 = detect_is64_block(ei);
        int e = blockIdx.x * blockDim.x + threadIdx.x;
        if (e >= N_EDGES) return;
        int c = edge_col(ei, e, is64);
        atomicAdd(&g_deg[c], w[e]);
        atomicAdd(&g_cnt[c], 1);
    } else {
        int i = (blockIdx.x - EDGE_BLOCKS) * blockDim.x + threadIdx.x;
        if (i < IN_DIM * HID_DIM) {
            int k = i / HID_DIM, n = i % HID_DIM;
            float v = W1[i];
            bf16 hi = __float2bfloat16(v);
            bf16 lo = __float2bfloat16(v - __bfloat162float(hi));
            g_w1th[n * IN_DIM + k] = hi;
            g_w1tl[n * IN_DIM + k] = lo;
        } else {
            int j = i - IN_DIM * HID_DIM;
            if (j >= HID_DIM * OUT_DIM) return;
            int k = j / OUT_DIM, n = j % OUT_DIM;
            float v = W2[j];
            bf16 hi = __float2bfloat16(v);
            bf16 lo = __float2bfloat16(v - __bfloat162float(hi));
            g_w2th[n * HID_DIM + k] = hi;
            g_w2tl[n * HID_DIM + k] = lo;
        }
    }
}

// -------------- launch 2: fused scan (brute block prefix) + dis ------------
#define SCAN_BLOCKS ((N_NODES + 1023) / 1024)   // 98

__global__ void __launch_bounds__(1024) k_scan_fused()
{
    int b = blockIdx.x, t = threadIdx.x;
    int i = b * 1024 + t;

    int partial = 0;
    {
        const int4* c4 = (const int4*)g_cnt;
        int lim = (b * 1024) >> 2;
        for (int j = t; j < lim; j += 1024) {
            int4 q = c4[j];
            partial += q.x + q.y + q.z + q.w;
        }
    }
#pragma unroll
    for (int o = 16; o > 0; o >>= 1)
        partial += __shfl_down_sync(0xffffffffu, partial, o);
    __shared__ int ws[32];
    __shared__ int s_base;
    if ((t & 31) == 0) ws[t >> 5] = partial;
    __syncthreads();
    if (t < 32) {
        int x = ws[t];
#pragma unroll
        for (int o = 16; o > 0; o >>= 1)
            x += __shfl_down_sync(0xffffffffu, x, o);
        if (t == 0) s_base = x;
    }

    int v = 0;
    if (i < N_NODES) {
        v = g_cnt[i];
        float d = g_deg[i];
        g_dis[i] = (d > 0.f) ? rsqrtf(d) : 0.f;
    }

    int inc = v;
#pragma unroll
    for (int o = 1; o < 32; o <<= 1) {
        int x = __shfl_up_sync(0xffffffffu, inc, o);
        if ((t & 31) >= o) inc += x;
    }
    __shared__ int ws2[32], wo[32];
    if ((t & 31) == 31) ws2[t >> 5] = inc;
    __syncthreads();
    if (t < 32) {
        int x = ws2[t];
        int e = x;
#pragma unroll
        for (int o = 1; o < 32; o <<= 1) {
            int y = __shfl_up_sync(0xffffffffu, e, o);
            if (t >= o) e += y;
        }
        wo[t] = e - x;
    }
    __syncthreads();
    int off = s_base + wo[t >> 5] + inc - v;
    if (i < N_NODES) { g_off[i] = off; g_cur[i] = off; }
    if (b == 0 && t == 0) g_off[N_NODES] = N_EDGES;
}

// --------------------------- launch 3: CSR place ----------------------------

__global__ void k_place(const void* __restrict__ ei,
                        const float* __restrict__ w)
{
    int is64 = detect_is64_block(ei);
    int e = blockIdx.x * blockDim.x + threadIdx.x;
    if (e >= N_EDGES) return;
    int r = edge_row(ei, e, is64);
    int c = edge_col(ei, e, is64);
    float nm = g_dis[r] * w[e] * g_dis[c];
    int pos = atomicAdd(&g_cur[c], 1);
    g_csr_src[pos] = r;
    g_csr_nrm[pos] = nm;
}

// ----------------------------- aggregation ---------------------------------
// 2 warps per node, each owns 64 dims; lane loads float2 (256B/warp/edge,
// fully coalesced). R14-shape inner loop (no pipelining - it regressed).

#define AGG_FMA2(acc, nm, v) \
    do { acc.x = fmaf(nm, v.x, acc.x); acc.y = fmaf(nm, v.y, acc.y); } while (0)

__device__ __forceinline__ float2 agg_gather2(const float* __restrict__ src,
                                              int beg, int end, int dimoff)
{
    const float* sp = src + dimoff;     // gather addr = sp + r*128
    float2 a0 = make_float2(0.f, 0.f);
    float2 a1 = make_float2(0.f, 0.f);
    float2 a2 = make_float2(0.f, 0.f);
    float2 a3 = make_float2(0.f, 0.f);
    int e = beg;
    for (; e + 4 <= end; e += 4) {
        int   r0 = g_csr_src[e],     r1 = g_csr_src[e + 1];
        int   r2 = g_csr_src[e + 2], r3 = g_csr_src[e + 3];
        float n0 = g_csr_nrm[e],     n1 = g_csr_nrm[e + 1];
        float n2 = g_csr_nrm[e + 2], n3 = g_csr_nrm[e + 3];
        float2 v0 = __ldg((const float2*)(sp + ((size_t)r0 << 7)));
        float2 v1 = __ldg((const float2*)(sp + ((size_t)r1 << 7)));
        float2 v2 = __ldg((const float2*)(sp + ((size_t)r2 << 7)));
        float2 v3 = __ldg((const float2*)(sp + ((size_t)r3 << 7)));
        AGG_FMA2(a0, n0, v0); AGG_FMA2(a1, n1, v1);
        AGG_FMA2(a2, n2, v2); AGG_FMA2(a3, n3, v3);
    }
    for (; e < end; e++) {
        int   r = g_csr_src[e];
        float n = g_csr_nrm[e];
        float2 v = __ldg((const float2*)(sp + ((size_t)r << 7)));
        AGG_FMA2(a0, n, v);
    }
    return make_float2(a0.x + a1.x + a2.x + a3.x,
                       a0.y + a1.y + a2.y + a3.y);
}

// launch 4 (profiled slot): agg(x) -> bf16 hi/lo split (2 warps per node)
__global__ void k_agg_in(const float* __restrict__ x)
{
    int gw = (blockIdx.x * blockDim.x + threadIdx.x) >> 5;
    int node = gw >> 1;
    if (node >= N_NODES) return;
    int lane = threadIdx.x & 31;
    int dimoff = (gw & 1) * 64 + lane * 2;
    float2 acc = agg_gather2(x, g_off[node], g_off[node + 1], dimoff);
    bf16 hx = __float2bfloat16(acc.x), hy = __float2bfloat16(acc.y);
    bf16 lx = __float2bfloat16(acc.x - __bfloat162float(hx));
    bf16 ly = __float2bfloat16(acc.y - __bfloat162float(hy));
    size_t o = (size_t)node * 128 + dimoff;
    *(ushort2*)(g_a1h + o) = make_ushort2(bf_bits(hx), bf_bits(hy));
    *(ushort2*)(g_a1l + o) = make_ushort2(bf_bits(lx), bf_bits(ly));
}

// launch 6: agg(g_h2) + b2 -> out ; also re-zero g_deg/g_cnt for next run
__global__ void k_agg_out(float* __restrict__ out,
                          const float* __restrict__ b2)
{
    int gt = blockIdx.x * blockDim.x + threadIdx.x;
    if (gt < N_NODES) { g_deg[gt] = 0.f; g_cnt[gt] = 0; }
    int gw = gt >> 5;
    int node = gw >> 1;
    if (node >= N_NODES) return;
    int lane = threadIdx.x & 31;
    int dimoff = (gw & 1) * 64 + lane * 2;
    float2 acc = agg_gather2(g_h2, g_off[node], g_off[node + 1], dimoff);
    float2 bv = *(const float2*)(b2 + dimoff);
    acc.x += bv.x; acc.y += bv.y;
    *(float2*)(out + (size_t)node * 128 + dimoff) = acc;
}

// ----------------------- fused GEMM1+GEMM2 (persistent) ---------------------
// Padded smem rows: LDT=136 elems (272B) for A1/W1/W2, LDT2=264 (528B) for h.

#define LDT 136
#define LDT2 264

#define F_A1H 0
#define F_A1L 17408                 // 128*136
#define F_W1H 34816
#define F_W1L 69632
#define F_HH  0                     // h overlays A1/W1 (phase-separated)
#define F_HL  33792                 // 128*264
#define F_W2H 69632                 // W2 halves overlay W1L tail
#define F_W2L 87040
#define FUSED_SMEM (104448 * 2)     // 208896 bytes

template <int ROWS>
__device__ __forceinline__ void load_tile_async_guard(
    uint32_t sbase, uint32_t smo, bf16* smbase_ptr, const bf16* __restrict__ g,
    int rowStart, int validRows, int gStride, int kStart, int tid)
{
#pragma unroll
    for (int it = 0; it < ROWS / 16; it++) {
        int c = it * 256 + tid;
        int r  = c >> 4;
        int cc = c & 15;
        if (r < validRows) {
            uint32_t saddr = sbase + (smo + r * LDT + cc * 8) * 2;
            cp_async16(saddr, g + (size_t)(rowStart + r) * gStride + kStart + cc * 8);
        } else {
            *(uint4*)(smbase_ptr + smo + r * LDT + cc * 8) =
                make_uint4(0u, 0u, 0u, 0u);
        }
    }
}

__global__ void __launch_bounds__(256, 1) k_gcn_fused(const float* __restrict__ b1)
{
    extern __shared__ bf16 sm[];
    const int tid  = threadIdx.x;
    const int lane = tid & 31;
    const int wid  = tid >> 5;
    const int wm   = wid >> 2;          // 0..1
    const int wn   = wid & 3;           // 0..3
    const uint32_t sbase = smem_u32(sm);

    const int aRow = lane & 15;
    const int aK   = (lane >> 4) << 3;
    const int bRowOff = (lane & 7) + (((lane >> 4) & 1) << 3);
    const int bKOff   = (((lane >> 3) & 1) << 3);

    float bb[8][2];
#pragma unroll
    for (int nt = 0; nt < 8; nt++) {
        int c0 = wn * 64 + nt * 8 + (lane & 3) * 2;
        bb[nt][0] = b1[c0];
        bb[nt][1] = b1[c0 + 1];
    }

    for (int mt_i = blockIdx.x; mt_i < MTILES; mt_i += GRID_P) {
        const int mBase = mt_i * 128;
        const int validRows = min(128, N_NODES - mBase);

        // ---- phase A: load A1 + W1 ----
        __syncthreads();
        load_tile_async_guard<128>(sbase, F_A1H, sm, g_a1h, mBase, validRows, 128, 0, tid);
        load_tile_async_guard<128>(sbase, F_A1L, sm, g_a1l, mBase, validRows, 128, 0, tid);
        load_tile_async_guard<256>(sbase, F_W1H, sm, g_w1th, 0, 256, 128, 0, tid);
        load_tile_async_guard<256>(sbase, F_W1L, sm, g_w1tl, 0, 256, 128, 0, tid);
        cp_commit();
        cp_wait0();
        __syncthreads();

        // ---- GEMM1 mainloop ----
        float d1[4][8][4];
#pragma unroll
        for (int i = 0; i < 4; i++)
#pragma unroll
            for (int j = 0; j < 8; j++)
#pragma unroll
                for (int r = 0; r < 4; r++) d1[i][j][r] = 0.f;

#pragma unroll
        for (int k16 = 0; k16 < 8; k16++) {
            uint32_t ah[4][4], al[4][4];
#pragma unroll
            for (int mt = 0; mt < 4; mt++) {
                int off = (wm * 64 + mt * 16 + aRow) * LDT + k16 * 16 + aK;
                ldmx4(ah[mt][0], ah[mt][1], ah[mt][2], ah[mt][3],
                      sbase + (F_A1H + off) * 2);
                ldmx4(al[mt][0], al[mt][1], al[mt][2], al[mt][3],
                      sbase + (F_A1L + off) * 2);
            }
#pragma unroll
            for (int ntp = 0; ntp < 4; ntp++) {
                int off = (wn * 64 + ntp * 16 + bRowOff) * LDT + k16 * 16 + bKOff;
                uint32_t bh0, bh1, bh2, bh3, bl0, bl1, bl2, bl3;
                ldmx4(bh0, bh1, bh2, bh3, sbase + (F_W1H + off) * 2);
                ldmx4(bl0, bl1, bl2, bl3, sbase + (F_W1L + off) * 2);
#pragma unroll
                for (int mt = 0; mt < 4; mt++) {
                    mma_bf16(d1[mt][2 * ntp],     ah[mt], bh0, bh1);
                    mma_bf16(d1[mt][2 * ntp],     ah[mt], bl0, bl1);
                    mma_bf16(d1[mt][2 * ntp],     al[mt], bh0, bh1);
                    mma_bf16(d1[mt][2 * ntp + 1], ah[mt], bh2, bh3);
                    mma_bf16(d1[mt][2 * ntp + 1], ah[mt], bl2, bl3);
                    mma_bf16(d1[mt][2 * ntp + 1], al[mt], bh2, bh3);
                }
            }
        }

        __syncthreads();

        // ---- phase B: prefetch W2 half0, then bias+relu+split -> smem h ----
        load_tile_async_guard<128>(sbase, F_W2H, sm, g_w2th, 0, 128, 256, 0, tid);
        load_tile_async_guard<128>(sbase, F_W2L, sm, g_w2tl, 0, 128, 256, 0, tid);
        cp_commit();

#pragma unroll
        for (int mt = 0; mt < 4; mt++) {
            int r0 = wm * 64 + mt * 16 + (lane >> 2);
#pragma unroll
            for (int nt = 0; nt < 8; nt++) {
                int c0 = wn * 64 + nt * 8 + (lane & 3) * 2;
#pragma unroll
                for (int half = 0; half < 2; half++) {
                    int row = r0 + half * 8;
                    float v0 = fmaxf(d1[mt][nt][half * 2 + 0] + bb[nt][0], 0.f);
                    float v1 = fmaxf(d1[mt][nt][half * 2 + 1] + bb[nt][1], 0.f);
                    bf16 h0 = __float2bfloat16(v0);
                    bf16 h1 = __float2bfloat16(v1);
                    bf16 l0 = __float2bfloat16(v0 - __bfloat162float(h0));
                    bf16 l1 = __float2bfloat16(v1 - __bfloat162float(h1));
                    *(uint32_t*)(sm + F_HH + row * LDT2 + c0) =
                        (uint32_t)bf_bits(h0) | ((uint32_t)bf_bits(h1) << 16);
                    *(uint32_t*)(sm + F_HL + row * LDT2 + c0) =
                        (uint32_t)bf_bits(l0) | ((uint32_t)bf_bits(l1) << 16);
                }
            }
        }
        cp_wait0();
        __syncthreads();

        // ---- GEMM2: two K-halves from smem h, W2 streamed ----
        float d2[4][4][4];
#pragma unroll
        for (int i = 0; i < 4; i++)
#pragma unroll
            for (int j = 0; j < 4; j++)
#pragma unroll
                for (int r = 0; r < 4; r++) d2[i][j][r] = 0.f;

#pragma unroll
        for (int kt = 0; kt < 2; kt++) {
            if (kt == 1) {
                __syncthreads();
                load_tile_async_guard<128>(sbase, F_W2H, sm, g_w2th, 0, 128, 256, 128, tid);
                load_tile_async_guard<128>(sbase, F_W2L, sm, g_w2tl, 0, 128, 256, 128, tid);
                cp_commit();
                cp_wait0();
                __syncthreads();
            }
            const int ktStart = kt * 128;
#pragma unroll
            for (int k16 = 0; k16 < 8; k16++) {
                uint32_t ah[4][4], al[4][4];
#pragma unroll
                for (int mt = 0; mt < 4; mt++) {
                    int off = (wm * 64 + mt * 16 + aRow) * LDT2
                            + ktStart + k16 * 16 + aK;
                    ldmx4(ah[mt][0], ah[mt][1], ah[mt][2], ah[mt][3],
                          sbase + (F_HH + off) * 2);
                    ldmx4(al[mt][0], al[mt][1], al[mt][2], al[mt][3],
                          sbase + (F_HL + off) * 2);
                }
#pragma unroll
                for (int ntp = 0; ntp < 2; ntp++) {
                    int off = (wn * 32 + ntp * 16 + bRowOff) * LDT + k16 * 16 + bKOff;
                    uint32_t bh0, bh1, bh2, bh3, bl0, bl1, bl2, bl3;
                    ldmx4(bh0, bh1, bh2, bh3, sbase + (F_W2H + off) * 2);
                    ldmx4(bl0, bl1, bl2, bl3, sbase + (F_W2L + off) * 2);
#pragma unroll
                    for (int mt = 0; mt < 4; mt++) {
                        mma_bf16(d2[mt][2 * ntp],     ah[mt], bh0, bh1);
                        mma_bf16(d2[mt][2 * ntp],     ah[mt], bl0, bl1);
                        mma_bf16(d2[mt][2 * ntp],     al[mt], bh0, bh1);
                        mma_bf16(d2[mt][2 * ntp + 1], ah[mt], bh2, bh3);
                        mma_bf16(d2[mt][2 * ntp + 1], ah[mt], bl2, bl3);
                        mma_bf16(d2[mt][2 * ntp + 1], al[mt], bh2, bh3);
                    }
                }
            }
        }

        // ---- epilogue 2: fp32 -> g_h2 ----
#pragma unroll
        for (int mt = 0; mt < 4; mt++) {
            int r0 = mBase + wm * 64 + mt * 16 + (lane >> 2);
#pragma unroll
            for (int nt = 0; nt < 4; nt++) {
                int c0 = wn * 32 + nt * 8 + (lane & 3) * 2;
#pragma unroll
                for (int half = 0; half < 2; half++) {
                    int row = r0 + half * 8;
                    if (row >= N_NODES) continue;
                    *(float2*)(g_h2 + (size_t)row * OUT_DIM + c0) =
                        make_float2(d2[mt][nt][half * 2 + 0],
                                    d2[mt][nt][half * 2 + 1]);
                }
            }
        }
    }
}

// -------------------------------- launcher ---------------------------------

extern "C" void kernel_launch(void* const* d_in, const int* in_sizes, int n_in,
                              void* d_out, int out_size)
{
    const float* x  = (const float*)d_in[0];
    const void*  ei = d_in[1];
    const float* w  = (const float*)d_in[2];
    const float* W1 = (const float*)d_in[3];
    const float* b1 = (const float*)d_in[4];
    const float* W2 = (const float*)d_in[5];
    const float* b2 = (const float*)d_in[6];
    float* out = (float*)d_out;

    // 2 warps per node -> 64 threads per node
    const int aggBlocks = (N_NODES * 64 + 255) / 256;   // 25000

    cudaFuncSetAttribute(k_gcn_fused,
        cudaFuncAttributeMaxDynamicSharedMemorySize, FUSED_SMEM);

    k_deg_prep<<<EDGE_BLOCKS + PREP_BLOCKS, 256>>>(ei, w, W1, W2);   // 1
    k_scan_fused<<<SCAN_BLOCKS, 1024>>>();                           // 2
    k_place<<<EDGE_BLOCKS, 256>>>(ei, w);                            // 3
    k_agg_in<<<aggBlocks, 256>>>(x);                                 // 4 <- profiled
    k_gcn_fused<<<GRID_P, 256, FUSED_SMEM>>>(b1);                    // 5
    k_agg_out<<<aggBlocks, 256>>>(out, b2);                          // 6
}

// round 17
// speedup vs baseline: 1.0173x; 1.0173x over previous
#include <cuda_runtime.h>
#include <cuda_bf16.h>
#include <cstddef>
#include <cstdint>

// ---------------------------------------------------------------------------
// SpatialGCN: 2-layer GCN, N=100000, E=800000, 128 -> 256 -> 128.
//   layer1: relu( agg(x) @ W1 + b1 )   [aggregate BEFORE GEMM, 128-dim]
//   layer2: agg( h @ W2 ) + b2         [aggregate AFTER GEMM, 128-dim]
// FUSED GEMM: one persistent kernel does GEMM1 -> (bias,relu,split) into
// SMEM -> GEMM2. mma.sync m16n8k16 bf16 hi/lo split, fp32 acc.
// Aggregation: R14-form gather (1 warp/node, float4, 4-edge unroll) over a
// PACKED int2 CSR (src, nrm) - one 8B store in place, one 8B load in gather.
// ---------------------------------------------------------------------------

#define N_NODES 100000
#define N_EDGES 800000
#define IN_DIM 128
#define HID_DIM 256
#define OUT_DIM 128
#define MTILES ((N_NODES + 127) / 128)     // 782
#define GRID_P 148

typedef __nv_bfloat16 bf16;

#define EDGE_BLOCKS ((N_EDGES + 255) / 256)
#define PREP_ELEMS (IN_DIM * HID_DIM + HID_DIM * OUT_DIM)
#define PREP_BLOCKS ((PREP_ELEMS + 255) / 256)

// -------------------- device scratch (static, no allocs) -------------------
__device__ float g_deg[N_NODES];           // zero at entry; re-zeroed at end
__device__ int   g_cnt[N_NODES];
__device__ float g_dis[N_NODES];
__device__ int   g_off[N_NODES + 1];
__device__ int   g_cur[N_NODES];
__device__ int2  g_csr[N_EDGES];           // packed {src, float_as_int(nrm)}

__device__ bf16  g_a1h[(size_t)N_NODES * IN_DIM];
__device__ bf16  g_a1l[(size_t)N_NODES * IN_DIM];
__device__ float g_h2[(size_t)N_NODES * OUT_DIM];

__device__ bf16  g_w1th[HID_DIM * IN_DIM];
__device__ bf16  g_w1tl[HID_DIM * IN_DIM];
__device__ bf16  g_w2th[OUT_DIM * HID_DIM];
__device__ bf16  g_w2tl[OUT_DIM * HID_DIM];

// ------------------------------ PTX helpers --------------------------------

__device__ __forceinline__ uint32_t smem_u32(const void* p)
{
    uint32_t a;
    asm("{ .reg .u64 t; cvta.to.shared.u64 t, %1; cvt.u32.u64 %0, t; }"
        : "=r"(a) : "l"(p));
    return a;
}

__device__ __forceinline__ void cp_async16(uint32_t saddr, const void* gptr)
{
    asm volatile("cp.async.cg.shared.global [%0], [%1], 16;"
                 :: "r"(saddr), "l"(__cvta_generic_to_global(gptr)));
}
__device__ __forceinline__ void cp_commit()
{
    asm volatile("cp.async.commit_group;");
}
__device__ __forceinline__ void cp_wait0()
{
    asm volatile("cp.async.wait_group 0;");
}

__device__ __forceinline__ void ldmx4(uint32_t& r0, uint32_t& r1,
                                      uint32_t& r2, uint32_t& r3, uint32_t a)
{
    asm volatile("ldmatrix.sync.aligned.m8n8.x4.shared.b16 {%0,%1,%2,%3}, [%4];"
                 : "=r"(r0), "=r"(r1), "=r"(r2), "=r"(r3) : "r"(a));
}

__device__ __forceinline__ void mma_bf16(float* d, const uint32_t* a,
                                         uint32_t b0, uint32_t b1)
{
    asm volatile(
        "mma.sync.aligned.m16n8k16.row.col.f32.bf16.bf16.f32 "
        "{%0,%1,%2,%3}, {%4,%5,%6,%7}, {%8,%9}, {%0,%1,%2,%3};"
        : "+f"(d[0]), "+f"(d[1]), "+f"(d[2]), "+f"(d[3])
        : "r"(a[0]), "r"(a[1]), "r"(a[2]), "r"(a[3]), "r"(b0), "r"(b1));
}

__device__ __forceinline__ unsigned short bf_bits(bf16 h)
{
    return *(unsigned short*)&h;
}

// --------------------- per-block edge-dtype detection ----------------------

__device__ __forceinline__ int detect_is64_block(const void* ei)
{
    __shared__ int s_is64;
    int t = threadIdx.x;
    int ok = 1;
    if (t < 16) {
        const long long* p = (const long long*)ei;
        long long a = p[t];
        long long b = p[N_EDGES + t];
        if (a < 0 || a >= N_NODES || b < 0 || b >= N_NODES) ok = 0;
    }
    unsigned bad = __ballot_sync(0xffffffffu, ok == 0);
    if (t == 0) s_is64 = (bad == 0u);
    __syncthreads();
    return s_is64;
}

__device__ __forceinline__ int edge_row(const void* ei, int e, int is64)
{
    if (is64) return (int)((const long long*)ei)[e];
    return ((const int*)ei)[e];
}
__device__ __forceinline__ int edge_col(const void* ei, int e, int is64)
{
    if (is64) return (int)((const long long*)ei)[N_EDGES + e];
    return ((const int*)ei)[N_EDGES + e];
}

// ---------------- launch 1: deg/cnt accumulation + weight prep -------------

__global__ void k_deg_prep(const void* __restrict__ ei,
                           const float* __restrict__ w,
                           const float* __restrict__ W1,
                           const float* __restrict__ W2)
{
    if (blockIdx.x < EDGE_BLOCKS) {
        int is64 = detect_is64_block(ei);
        int e = blockIdx.x * blockDim.x + threadIdx.x;
        if (e >= N_EDGES) return;
        int c = edge_col(ei, e, is64);
        atomicAdd(&g_deg[c], w[e]);
        atomicAdd(&g_cnt[c], 1);
    } else {
        int i = (blockIdx.x - EDGE_BLOCKS) * blockDim.x + threadIdx.x;
        if (i < IN_DIM * HID_DIM) {
            int k = i / HID_DIM, n = i % HID_DIM;
            float v = W1[i];
            bf16 hi = __float2bfloat16(v);
            bf16 lo = __float2bfloat16(v - __bfloat162float(hi));
            g_w1th[n * IN_DIM + k] = hi;
            g_w1tl[n * IN_DIM + k] = lo;
        } else {
            int j = i - IN_DIM * HID_DIM;
            if (j >= HID_DIM * OUT_DIM) return;
            int k = j / OUT_DIM, n = j % OUT_DIM;
            float v = W2[j];
            bf16 hi = __float2bfloat16(v);
            bf16 lo = __float2bfloat16(v - __bfloat162float(hi));
            g_w2th[n * HID_DIM + k] = hi;
            g_w2tl[n * HID_DIM + k] = lo;
        }
    }
}

// -------------- launch 2: fused scan (brute block prefix) + dis ------------
#define SCAN_BLOCKS ((N_NODES + 1023) / 1024)   // 98

__global__ void __launch_bounds__(1024) k_scan_fused()
{
    int b = blockIdx.x, t = threadIdx.x;
    int i = b * 1024 + t;

    int partial = 0;
    {
        const int4* c4 = (const int4*)g_cnt;
        int lim = (b * 1024) >> 2;
        for (int j = t; j < lim; j += 1024) {
            int4 q = c4[j];
            partial += q.x + q.y + q.z + q.w;
        }
    }
#pragma unroll
    for (int o = 16; o > 0; o >>= 1)
        partial += __shfl_down_sync(0xffffffffu, partial, o);
    __shared__ int ws[32];
    __shared__ int s_base;
    if ((t & 31) == 0) ws[t >> 5] = partial;
    __syncthreads();
    if (t < 32) {
        int x = ws[t];
#pragma unroll
        for (int o = 16; o > 0; o >>= 1)
            x += __shfl_down_sync(0xffffffffu, x, o);
        if (t == 0) s_base = x;
    }

    int v = 0;
    if (i < N_NODES) {
        v = g_cnt[i];
        float d = g_deg[i];
        g_dis[i] = (d > 0.f) ? rsqrtf(d) : 0.f;
    }

    int inc = v;
#pragma unroll
    for (int o = 1; o < 32; o <<= 1) {
        int x = __shfl_up_sync(0xffffffffu, inc, o);
        if ((t & 31) >= o) inc += x;
    }
    __shared__ int ws2[32], wo[32];
    if ((t & 31) == 31) ws2[t >> 5] = inc;
    __syncthreads();
    if (t < 32) {
        int x = ws2[t];
        int e = x;
#pragma unroll
        for (int o = 1; o < 32; o <<= 1) {
            int y = __shfl_up_sync(0xffffffffu, e, o);
            if (t >= o) e += y;
        }
        wo[t] = e - x;
    }
    __syncthreads();
    int off = s_base + wo[t >> 5] + inc - v;
    if (i < N_NODES) { g_off[i] = off; g_cur[i] = off; }
    if (b == 0 && t == 0) g_off[N_NODES] = N_EDGES;
}

// --------------------------- launch 3: CSR place ----------------------------

__global__ void k_place(const void* __restrict__ ei,
                        const float* __restrict__ w)
{
    int is64 = detect_is64_block(ei);
    int e = blockIdx.x * blockDim.x + threadIdx.x;
    if (e >= N_EDGES) return;
    int r = edge_row(ei, e, is64);
    int c = edge_col(ei, e, is64);
    float nm = __ldg(&g_dis[r]) * w[e] * __ldg(&g_dis[c]);
    int pos = atomicAdd(&g_cur[c], 1);
    g_csr[pos] = make_int2(r, __float_as_int(nm));   // single 8B random store
}

// ----------------------------- aggregation ---------------------------------
// R14 form: 1 warp/node, float4 lanes, 4-edge unroll, packed int2 CSR.

#define AGG_FMA4(acc, nm, v) \
    do { acc.x = fmaf(nm, v.x, acc.x); acc.y = fmaf(nm, v.y, acc.y); \
         acc.z = fmaf(nm, v.z, acc.z); acc.w = fmaf(nm, v.w, acc.w); } while (0)

__device__ __forceinline__ float4 agg_gather(const float* __restrict__ src,
                                             int beg, int end, int lane)
{
    const float* sp = src + lane * 4;
    float4 a0 = make_float4(0.f, 0.f, 0.f, 0.f);
    float4 a1 = make_float4(0.f, 0.f, 0.f, 0.f);
    float4 a2 = make_float4(0.f, 0.f, 0.f, 0.f);
    float4 a3 = make_float4(0.f, 0.f, 0.f, 0.f);
    int e = beg;
    for (; e + 4 <= end; e += 4) {
        int2 p0 = g_csr[e],     p1 = g_csr[e + 1];
        int2 p2 = g_csr[e + 2], p3 = g_csr[e + 3];
        float4 v0 = __ldg((const float4*)(sp + ((size_t)p0.x << 7)));
        float4 v1 = __ldg((const float4*)(sp + ((size_t)p1.x << 7)));
        float4 v2 = __ldg((const float4*)(sp + ((size_t)p2.x << 7)));
        float4 v3 = __ldg((const float4*)(sp + ((size_t)p3.x << 7)));
        AGG_FMA4(a0, __int_as_float(p0.y), v0);
        AGG_FMA4(a1, __int_as_float(p1.y), v1);
        AGG_FMA4(a2, __int_as_float(p2.y), v2);
        AGG_FMA4(a3, __int_as_float(p3.y), v3);
    }
    for (; e < end; e++) {
        int2 p = g_csr[e];
        float4 v = __ldg((const float4*)(sp + ((size_t)p.x << 7)));
        AGG_FMA4(a0, __int_as_float(p.y), v);
    }
    return make_float4(a0.x + a1.x + a2.x + a3.x,
                       a0.y + a1.y + a2.y + a3.y,
                       a0.z + a1.z + a2.z + a3.z,
                       a0.w + a1.w + a2.w + a3.w);
}

// launch 4 (profiled slot): agg(x) -> bf16 hi/lo split (1 warp per node)
__global__ void k_agg_in(const float* __restrict__ x)
{
    int gw = (blockIdx.x * blockDim.x + threadIdx.x) >> 5;
    if (gw >= N_NODES) return;
    int lane = threadIdx.x & 31;
    float4 acc = agg_gather(x, g_off[gw], g_off[gw + 1], lane);
    bf16 hx = __float2bfloat16(acc.x), hy = __float2bfloat16(acc.y);
    bf16 hz = __float2bfloat16(acc.z), hw = __float2bfloat16(acc.w);
    bf16 lx = __float2bfloat16(acc.x - __bfloat162float(hx));
    bf16 ly = __float2bfloat16(acc.y - __bfloat162float(hy));
    bf16 lz = __float2bfloat16(acc.z - __bfloat162float(hz));
    bf16 lw = __float2bfloat16(acc.w - __bfloat162float(hw));
    size_t o = (size_t)gw * 128 + lane * 4;
    *(ushort4*)(g_a1h + o) = make_ushort4(bf_bits(hx), bf_bits(hy), bf_bits(hz), bf_bits(hw));
    *(ushort4*)(g_a1l + o) = make_ushort4(bf_bits(lx), bf_bits(ly), bf_bits(lz), bf_bits(lw));
}

// launch 6: agg(g_h2) + b2 -> out ; also re-zero g_deg/g_cnt for next run
__global__ void k_agg_out(float* __restrict__ out,
                          const float* __restrict__ b2)
{
    int gt = blockIdx.x * blockDim.x + threadIdx.x;
    if (gt < N_NODES) { g_deg[gt] = 0.f; g_cnt[gt] = 0; }
    int gw = gt >> 5;
    if (gw >= N_NODES) return;
    int lane = threadIdx.x & 31;
    float4 acc = agg_gather(g_h2, g_off[gw], g_off[gw + 1], lane);
    float4 bv = *(const float4*)(b2 + lane * 4);
    acc.x += bv.x; acc.y += bv.y; acc.z += bv.z; acc.w += bv.w;
    *(float4*)(out + (size_t)gw * 128 + lane * 4) = acc;
}

// ----------------------- fused GEMM1+GEMM2 (persistent) ---------------------
// Padded smem rows: LDT=136 elems (272B) for A1/W1/W2, LDT2=264 (528B) for h.

#define LDT 136
#define LDT2 264

#define F_A1H 0
#define F_A1L 17408                 // 128*136
#define F_W1H 34816
#define F_W1L 69632
#define F_HH  0                     // h overlays A1/W1 (phase-separated)
#define F_HL  33792                 // 128*264
#define F_W2H 69632                 // W2 halves overlay W1L tail
#define F_W2L 87040
#define FUSED_SMEM (104448 * 2)     // 208896 bytes

template <int ROWS>
__device__ __forceinline__ void load_tile_async_guard(
    uint32_t sbase, uint32_t smo, bf16* smbase_ptr, const bf16* __restrict__ g,
    int rowStart, int validRows, int gStride, int kStart, int tid)
{
#pragma unroll
    for (int it = 0; it < ROWS / 16; it++) {
        int c = it * 256 + tid;
        int r  = c >> 4;
        int cc = c & 15;
        if (r < validRows) {
            uint32_t saddr = sbase + (smo + r * LDT + cc * 8) * 2;
            cp_async16(saddr, g + (size_t)(rowStart + r) * gStride + kStart + cc * 8);
        } else {
            *(uint4*)(smbase_ptr + smo + r * LDT + cc * 8) =
                make_uint4(0u, 0u, 0u, 0u);
        }
    }
}

__global__ void __launch_bounds__(256, 1) k_gcn_fused(const float* __restrict__ b1)
{
    extern __shared__ bf16 sm[];
    const int tid  = threadIdx.x;
    const int lane = tid & 31;
    const int wid  = tid >> 5;
    const int wm   = wid >> 2;          // 0..1
    const int wn   = wid & 3;           // 0..3
    const uint32_t sbase = smem_u32(sm);

    const int aRow = lane & 15;
    const int aK   = (lane >> 4) << 3;
    const int bRowOff = (lane & 7) + (((lane >> 4) & 1) << 3);
    const int bKOff   = (((lane >> 3) & 1) << 3);

    float bb[8][2];
#pragma unroll
    for (int nt = 0; nt < 8; nt++) {
        int c0 = wn * 64 + nt * 8 + (lane & 3) * 2;
        bb[nt][0] = b1[c0];
        bb[nt][1] = b1[c0 + 1];
    }

    for (int mt_i = blockIdx.x; mt_i < MTILES; mt_i += GRID_P) {
        const int mBase = mt_i * 128;
        const int validRows = min(128, N_NODES - mBase);

        // ---- phase A: load A1 + W1 ----
        __syncthreads();
        load_tile_async_guard<128>(sbase, F_A1H, sm, g_a1h, mBase, validRows, 128, 0, tid);
        load_tile_async_guard<128>(sbase, F_A1L, sm, g_a1l, mBase, validRows, 128, 0, tid);
        load_tile_async_guard<256>(sbase, F_W1H, sm, g_w1th, 0, 256, 128, 0, tid);
        load_tile_async_guard<256>(sbase, F_W1L, sm, g_w1tl, 0, 256, 128, 0, tid);
        cp_commit();
        cp_wait0();
        __syncthreads();

        // ---- GEMM1 mainloop ----
        float d1[4][8][4];
#pragma unroll
        for (int i = 0; i < 4; i++)
#pragma unroll
            for (int j = 0; j < 8; j++)
#pragma unroll
                for (int r = 0; r < 4; r++) d1[i][j][r] = 0.f;

#pragma unroll
        for (int k16 = 0; k16 < 8; k16++) {
            uint32_t ah[4][4], al[4][4];
#pragma unroll
            for (int mt = 0; mt < 4; mt++) {
                int off = (wm * 64 + mt * 16 + aRow) * LDT + k16 * 16 + aK;
                ldmx4(ah[mt][0], ah[mt][1], ah[mt][2], ah[mt][3],
                      sbase + (F_A1H + off) * 2);
                ldmx4(al[mt][0], al[mt][1], al[mt][2], al[mt][3],
                      sbase + (F_A1L + off) * 2);
            }
#pragma unroll
            for (int ntp = 0; ntp < 4; ntp++) {
                int off = (wn * 64 + ntp * 16 + bRowOff) * LDT + k16 * 16 + bKOff;
                uint32_t bh0, bh1, bh2, bh3, bl0, bl1, bl2, bl3;
                ldmx4(bh0, bh1, bh2, bh3, sbase + (F_W1H + off) * 2);
                ldmx4(bl0, bl1, bl2, bl3, sbase + (F_W1L + off) * 2);
#pragma unroll
                for (int mt = 0; mt < 4; mt++) {
                    mma_bf16(d1[mt][2 * ntp],     ah[mt], bh0, bh1);
                    mma_bf16(d1[mt][2 * ntp],     ah[mt], bl0, bl1);
                    mma_bf16(d1[mt][2 * ntp],     al[mt], bh0, bh1);
                    mma_bf16(d1[mt][2 * ntp + 1], ah[mt], bh2, bh3);
                    mma_bf16(d1[mt][2 * ntp + 1], ah[mt], bl2, bl3);
                    mma_bf16(d1[mt][2 * ntp + 1], al[mt], bh2, bh3);
                }
            }
        }

        __syncthreads();

        // ---- phase B: prefetch W2 half0, then bias+relu+split -> smem h ----
        load_tile_async_guard<128>(sbase, F_W2H, sm, g_w2th, 0, 128, 256, 0, tid);
        load_tile_async_guard<128>(sbase, F_W2L, sm, g_w2tl, 0, 128, 256, 0, tid);
        cp_commit();

#pragma unroll
        for (int mt = 0; mt < 4; mt++) {
            int r0 = wm * 64 + mt * 16 + (lane >> 2);
#pragma unroll
            for (int nt = 0; nt < 8; nt++) {
                int c0 = wn * 64 + nt * 8 + (lane & 3) * 2;
#pragma unroll
                for (int half = 0; half < 2; half++) {
                    int row = r0 + half * 8;
                    float v0 = fmaxf(d1[mt][nt][half * 2 + 0] + bb[nt][0], 0.f);
                    float v1 = fmaxf(d1[mt][nt][half * 2 + 1] + bb[nt][1], 0.f);
                    bf16 h0 = __float2bfloat16(v0);
                    bf16 h1 = __float2bfloat16(v1);
                    bf16 l0 = __float2bfloat16(v0 - __bfloat162float(h0));
                    bf16 l1 = __float2bfloat16(v1 - __bfloat162float(h1));
                    *(uint32_t*)(sm + F_HH + row * LDT2 + c0) =
                        (uint32_t)bf_bits(h0) | ((uint32_t)bf_bits(h1) << 16);
                    *(uint32_t*)(sm + F_HL + row * LDT2 + c0) =
                        (uint32_t)bf_bits(l0) | ((uint32_t)bf_bits(l1) << 16);
                }
            }
        }
        cp_wait0();
        __syncthreads();

        // ---- GEMM2: two K-halves from smem h, W2 streamed ----
        float d2[4][4][4];
#pragma unroll
        for (int i = 0; i < 4; i++)
#pragma unroll
            for (int j = 0; j < 4; j++)
#pragma unroll
                for (int r = 0; r < 4; r++) d2[i][j][r] = 0.f;

#pragma unroll
        for (int kt = 0; kt < 2; kt++) {
            if (kt == 1) {
                __syncthreads();
                load_tile_async_guard<128>(sbase, F_W2H, sm, g_w2th, 0, 128, 256, 128, tid);
                load_tile_async_guard<128>(sbase, F_W2L, sm, g_w2tl, 0, 128, 256, 128, tid);
                cp_commit();
                cp_wait0();
                __syncthreads();
            }
            const int ktStart = kt * 128;
#pragma unroll
            for (int k16 = 0; k16 < 8; k16++) {
                uint32_t ah[4][4], al[4][4];
#pragma unroll
                for (int mt = 0; mt < 4; mt++) {
                    int off = (wm * 64 + mt * 16 + aRow) * LDT2
                            + ktStart + k16 * 16 + aK;
                    ldmx4(ah[mt][0], ah[mt][1], ah[mt][2], ah[mt][3],
                          sbase + (F_HH + off) * 2);
                    ldmx4(al[mt][0], al[mt][1], al[mt][2], al[mt][3],
                          sbase + (F_HL + off) * 2);
                }
#pragma unroll
                for (int ntp = 0; ntp < 2; ntp++) {
                    int off = (wn * 32 + ntp * 16 + bRowOff) * LDT + k16 * 16 + bKOff;
                    uint32_t bh0, bh1, bh2, bh3, bl0, bl1, bl2, bl3;
                    ldmx4(bh0, bh1, bh2, bh3, sbase + (F_W2H + off) * 2);
                    ldmx4(bl0, bl1, bl2, bl3, sbase + (F_W2L + off) * 2);
#pragma unroll
                    for (int mt = 0; mt < 4; mt++) {
                        mma_bf16(d2[mt][2 * ntp],     ah[mt], bh0, bh1);
                        mma_bf16(d2[mt][2 * ntp],     ah[mt], bl0, bl1);
                        mma_bf16(d2[mt][2 * ntp],     al[mt], bh0, bh1);
                        mma_bf16(d2[mt][2 * ntp + 1], ah[mt], bh2, bh3);
                        mma_bf16(d2[mt][2 * ntp + 1], ah[mt], bl2, bl3);
                        mma_bf16(d2[mt][2 * ntp + 1], al[mt], bh2, bh3);
                    }
                }
            }
        }

        // ---- epilogue 2: fp32 -> g_h2 ----
#pragma unroll
        for (int mt = 0; mt < 4; mt++) {
            int r0 = mBase + wm * 64 + mt * 16 + (lane >> 2);
#pragma unroll
            for (int nt = 0; nt < 4; nt++) {
                int c0 = wn * 32 + nt * 8 + (lane & 3) * 2;
#pragma unroll
                for (int half = 0; half < 2; half++) {
                    int row = r0 + half * 8;
                    if (row >= N_NODES) continue;
                    *(float2*)(g_h2 + (size_t)row * OUT_DIM + c0) =
                        make_float2(d2[mt][nt][half * 2 + 0],
                                    d2[mt][nt][half * 2 + 1]);
                }
            }
        }
    }
}

// -------------------------------- launcher ---------------------------------

extern "C" void kernel_launch(void* const* d_in, const int* in_sizes, int n_in,
                              void* d_out, int out_size)
{
    const float* x  = (const float*)d_in[0];
    const void*  ei = d_in[1];
    const float* w  = (const float*)d_in[2];
    const float* W1 = (const float*)d_in[3];
    const float* b1 = (const float*)d_in[4];
    const float* W2 = (const float*)d_in[5];
    const float* b2 = (const float*)d_in[6];
    float* out = (float*)d_out;

    const int aggBlocks = (N_NODES * 32 + 255) / 256;   // 12500

    cudaFuncSetAttribute(k_gcn_fused,
        cudaFuncAttributeMaxDynamicSharedMemorySize, FUSED_SMEM);

    k_deg_prep<<<EDGE_BLOCKS + PREP_BLOCKS, 256>>>(ei, w, W1, W2);   // 1
    k_scan_fused<<<SCAN_BLOCKS, 1024>>>();                           // 2
    k_place<<<EDGE_BLOCKS, 256>>>(ei, w);                            // 3
    k_agg_in<<<aggBlocks, 256>>>(x);                                 // 4 <- profiled
    k_gcn_fused<<<GRID_P, 256, FUSED_SMEM>>>(b1);                    // 5
    k_agg_out<<<aggBlocks, 256>>>(out, b2);                          // 6
}